// round 1
// baseline (speedup 1.0000x reference)
#include <cuda_runtime.h>
#include <math.h>

#define BB 4
#define CIN 64
#define HH 128
#define WW 128
#define HWSZ (HH*WW)
#define COUT 64
#define K9 9
#define C27 27
#define CK 576  // CIN*K9

// Scratch (device globals: no allocation allowed in kernel_launch)
__device__ float g_om[BB*C27*HWSZ];   // offset-conv output: dy(0..8), dx(9..17), sigmoid(mask)(18..26)
__device__ float g_wT[CK*COUT];       // main weight transposed: [c*9+k][oc]
__device__ float g_owT[CK*28];        // offset weight transposed + padded: [c*9+k][oc(28)]

// ---------------------------------------------------------------------------
// Kernel 0: transpose weights into gather-friendly layouts
// ---------------------------------------------------------------------------
__global__ void prep_kernel(const float* __restrict__ wt, const float* __restrict__ owt) {
    int idx = blockIdx.x * blockDim.x + threadIdx.x;
    if (idx < CK*COUT) {
        int o  = idx & 63;
        int ck = idx >> 6;
        g_wT[idx] = wt[o*CK + ck];
    }
    if (idx < CK*28) {
        int o  = idx % 28;
        int ck = idx / 28;
        g_owT[idx] = (o < C27) ? owt[o*CK + ck] : 0.f;
    }
}

// ---------------------------------------------------------------------------
// Kernel 1: offset/mask conv (ordinary 3x3, stride1 pad1), 27 out channels.
// One thread per output pixel; 27 accumulators; weights read as broadcast
// float4 from the transposed [ck][28] layout.
// ---------------------------------------------------------------------------
__global__ __launch_bounds__(128) void offset_kernel(const float* __restrict__ x,
                                                     const float* __restrict__ ob) {
    int p  = blockIdx.x * blockDim.x + threadIdx.x;
    int b  = p >> 14;
    int hw = p & (HWSZ - 1);
    int h  = hw >> 7;
    int w  = hw & 127;

    float acc[28];
    #pragma unroll
    for (int o = 0; o < C27; o++) acc[o] = __ldg(ob + o);
    acc[27] = 0.f;

    // 3x3 neighborhood (zero-padded): indices + validity, pixel-invariant over c
    int  nidx[9];
    bool nval[9];
    #pragma unroll
    for (int kh = 0; kh < 3; kh++) {
        #pragma unroll
        for (int kw = 0; kw < 3; kw++) {
            int hh = h - 1 + kh;
            int ww = w - 1 + kw;
            bool v = (hh >= 0) && (hh < HH) && (ww >= 0) && (ww < WW);
            nidx[kh*3+kw] = v ? (hh*WW + ww) : 0;
            nval[kh*3+kw] = v;
        }
    }

    const float* xb = x + (size_t)b * CIN * HWSZ;
    #pragma unroll 1
    for (int c = 0; c < CIN; c++) {
        const float* xc = xb + c * HWSZ;
        float xv[9];
        #pragma unroll
        for (int k = 0; k < 9; k++) xv[k] = nval[k] ? __ldg(xc + nidx[k]) : 0.f;
        #pragma unroll
        for (int k = 0; k < 9; k++) {
            float v = xv[k];
            const float4* wp = (const float4*)(g_owT + (c*9 + k) * 28);
            #pragma unroll
            for (int q = 0; q < 7; q++) {
                float4 w4 = __ldg(wp + q);
                acc[4*q+0] = fmaf(v, w4.x, acc[4*q+0]);
                acc[4*q+1] = fmaf(v, w4.y, acc[4*q+1]);
                acc[4*q+2] = fmaf(v, w4.z, acc[4*q+2]);
                acc[4*q+3] = fmaf(v, w4.w, acc[4*q+3]);
            }
        }
    }

    float* om = g_om + (size_t)b * C27 * HWSZ + hw;
    #pragma unroll
    for (int o = 0; o < 18; o++) om[o*HWSZ] = acc[o];
    #pragma unroll
    for (int o = 18; o < C27; o++) om[o*HWSZ] = 1.f / (1.f + expf(-acc[o]));
}

// ---------------------------------------------------------------------------
// Kernel 2: deformable sampling + implicit GEMM.
// One thread per output pixel, 64 f32 accumulators (all out channels).
// Per tap k: bilinear corners/weights computed once (channel-independent),
// validity + mask folded into the 4 weights. Per channel: 4 gathers + 4 FMA
// -> modulated column value -> 64 FMAs against transposed weights (16x LDG.128
// broadcast).
// ---------------------------------------------------------------------------
__global__ __launch_bounds__(128) void dcn_kernel(const float* __restrict__ x,
                                                  const float* __restrict__ bias,
                                                  float* __restrict__ out) {
    int p  = blockIdx.x * blockDim.x + threadIdx.x;
    int b  = p >> 14;
    int hw = p & (HWSZ - 1);
    int h  = hw >> 7;
    int w  = hw & 127;

    float acc[COUT];
    #pragma unroll
    for (int q = 0; q < 16; q++) {
        float4 b4 = __ldg((const float4*)bias + q);
        acc[4*q+0] = b4.x; acc[4*q+1] = b4.y; acc[4*q+2] = b4.z; acc[4*q+3] = b4.w;
    }

    const float* xb  = x + (size_t)b * CIN * HWSZ;
    const float* omb = g_om + (size_t)b * C27 * HWSZ + hw;

    #pragma unroll 1
    for (int k = 0; k < 9; k++) {
        float dy = __ldg(omb + k*HWSZ);
        float dx = __ldg(omb + (9 + k)*HWSZ);
        float m  = __ldg(omb + (18 + k)*HWSZ);
        int kh = k / 3;
        int kw = k - kh*3;
        float hh = (float)(h - 1 + kh) + dy;
        float ww = (float)(w - 1 + kw) + dx;
        float h0f = floorf(hh), w0f = floorf(ww);
        float lh = hh - h0f,   lw = ww - w0f;
        int h0 = (int)h0f, w0 = (int)w0f;
        int h1 = h0 + 1,  w1 = w0 + 1;
        bool vh0 = (h0 >= 0) && (h0 < HH);
        bool vh1 = (h1 >= 0) && (h1 < HH);
        bool vw0 = (w0 >= 0) && (w0 < WW);
        bool vw1 = (w1 >= 0) && (w1 < WW);
        int ch0 = min(max(h0, 0), HH-1), ch1 = min(max(h1, 0), HH-1);
        int cw0 = min(max(w0, 0), WW-1), cw1 = min(max(w1, 0), WW-1);
        int i00 = ch0*WW + cw0, i01 = ch0*WW + cw1;
        int i10 = ch1*WW + cw0, i11 = ch1*WW + cw1;
        float w00 = (1.f - lh) * (1.f - lw) * m * ((vh0 && vw0) ? 1.f : 0.f);
        float w01 = (1.f - lh) * lw         * m * ((vh0 && vw1) ? 1.f : 0.f);
        float w10 = lh * (1.f - lw)         * m * ((vh1 && vw0) ? 1.f : 0.f);
        float w11 = lh * lw                 * m * ((vh1 && vw1) ? 1.f : 0.f);

        const float* xc = xb;
        #pragma unroll 2
        for (int c = 0; c < CIN; c++) {
            float val = w00 * __ldg(xc + i00);
            val = fmaf(w01, __ldg(xc + i01), val);
            val = fmaf(w10, __ldg(xc + i10), val);
            val = fmaf(w11, __ldg(xc + i11), val);
            const float4* wpc = (const float4*)(g_wT + (c*9 + k) * COUT);
            #pragma unroll
            for (int q = 0; q < 16; q++) {
                float4 w4 = __ldg(wpc + q);
                acc[4*q+0] = fmaf(val, w4.x, acc[4*q+0]);
                acc[4*q+1] = fmaf(val, w4.y, acc[4*q+1]);
                acc[4*q+2] = fmaf(val, w4.z, acc[4*q+2]);
                acc[4*q+3] = fmaf(val, w4.w, acc[4*q+3]);
            }
            xc += HWSZ;
        }
    }

    float* ob = out + (size_t)b * COUT * HWSZ + hw;
    #pragma unroll
    for (int o = 0; o < COUT; o++) ob[o*HWSZ] = acc[o];
}

// ---------------------------------------------------------------------------
extern "C" void kernel_launch(void* const* d_in, const int* in_sizes, int n_in,
                              void* d_out, int out_size) {
    const float* x    = (const float*)d_in[0];  // [4,64,128,128]
    const float* wt   = (const float*)d_in[1];  // [64,64,3,3]
    const float* bias = (const float*)d_in[2];  // [64]
    const float* owt  = (const float*)d_in[3];  // [27,64,3,3]
    const float* ob   = (const float*)d_in[4];  // [27]
    float* out = (float*)d_out;                 // [4,64,128,128]

    prep_kernel<<<(CK*COUT + 255) / 256, 256>>>(wt, owt);
    offset_kernel<<<BB*HWSZ/128, 128>>>(x, ob);
    dcn_kernel<<<BB*HWSZ/128, 128>>>(x, bias, out);
}